// round 11
// baseline (speedup 1.0000x reference)
#include <cuda_runtime.h>
#include <cuda_bf16.h>
#include <cstdint>

// TSM: x (B=4, T=16, H=64, W=64, C=256) fp32
// out[..., 0:64)    = x[t+1, ..., 0:64)   (0 at t=T-1)
// out[..., 64:128)  = x[t-1, ..., 64:128) (0 at t=0)
// out[..., 128:256) = x[t, ..., 128:256)
//
// R11: final micro-sweep — identical structure to the converged config
// (block-strided unroll x8, .cs load/store, exact-fit grid), TPB 256 -> 512
// (4096 CTAs instead of 8192: half the wave transitions / CTA setup, same
// byte-identical access pattern, same RF-limited per-SM residency).
//
// Plateau evidence (R1-R10): all variants pin at 6.33-6.47 TB/s == B300 LTS
// chip cap (~6300 B/cyc, path-independent). SM pipes <9%. Traffic minimal.
//
// float4 units: c4 = i & 63; t = (i >> 18) & 15; slab stride = 1<<18 float4.
// dt = +1 (c4<16), -1 (c4<32), 0 otherwise. Invalid src -> 0.

static constexpr int BTSTRIDE = 1 << 18;      // float4 per (b,t) slab
static constexpr long long N4 = 16777216LL;   // total float4
static constexpr int UNROLL = 8;
static constexpr int TPB = 512;
static constexpr int F4_PER_BLOCK = TPB * UNROLL; // 4096

__global__ __launch_bounds__(TPB) void tsm_kernel(const float4* __restrict__ in,
                                                  float4* __restrict__ out)
{
    long long blockBase = (long long)(blockIdx.x) * F4_PER_BLOCK;
    int tid = threadIdx.x;

    float4 v[UNROLL];

    #pragma unroll
    for (int u = 0; u < UNROLL; ++u) {
        long long i = blockBase + u * TPB + tid;
        int c4 = (int)(i & 63);
        int t  = (int)((i >> 18) & 15);

        int dt = (c4 < 16) ? 1 : ((c4 < 32) ? -1 : 0);
        int ts = t + dt;
        bool valid = (unsigned)ts < 16u;

        v[u] = make_float4(0.f, 0.f, 0.f, 0.f);
        if (valid) {
            v[u] = __ldcs(&in[i + (long long)dt * BTSTRIDE]);
        }
    }

    #pragma unroll
    for (int u = 0; u < UNROLL; ++u) {
        long long i = blockBase + u * TPB + tid;
        __stcs(&out[i], v[u]);
    }
}

extern "C" void kernel_launch(void* const* d_in, const int* in_sizes, int n_in,
                              void* d_out, int out_size)
{
    const float4* in = (const float4*)d_in[0];
    float4* out = (float4*)d_out;

    int blocks = (int)(N4 / F4_PER_BLOCK); // 4096
    tsm_kernel<<<blocks, TPB>>>(in, out);
}

// round 12
// speedup vs baseline: 1.0004x; 1.0004x over previous
#include <cuda_runtime.h>
#include <cuda_bf16.h>
#include <cstdint>

// TSM: x (B=4, T=16, H=64, W=64, C=256) fp32
// out[..., 0:64)    = x[t+1, ..., 0:64)   (0 at t=T-1)
// out[..., 64:128)  = x[t-1, ..., 64:128) (0 at t=0)
// out[..., 128:256) = x[t, ..., 128:256)
//
// R12: continue the CTA-count trend (8192 blk @73.5us -> 4096 blk @72.7us):
// TPB=1024, unroll x8 -> 2048 blocks, each covering a 128KiB contiguous span.
// Occupancy drops to 1 CTA/SM (50%) but R1-R11 showed occupancy 50-89% is
// irrelevant (per-thread MLP=8 feeds the load queue either way).
//
// Plateau evidence (R1-R11): all variants pin at 6.33-6.51 TB/s == B300 LTS
// chip cap (~6300 B/cyc, path-independent). SM pipes <9%. Traffic minimal.
//
// float4 units: c4 = i & 63; t = (i >> 18) & 15; slab stride = 1<<18 float4.
// dt = +1 (c4<16), -1 (c4<32), 0 otherwise. Invalid src -> 0.

static constexpr int BTSTRIDE = 1 << 18;      // float4 per (b,t) slab
static constexpr long long N4 = 16777216LL;   // total float4
static constexpr int UNROLL = 8;
static constexpr int TPB = 1024;
static constexpr int F4_PER_BLOCK = TPB * UNROLL; // 8192

__global__ __launch_bounds__(TPB) void tsm_kernel(const float4* __restrict__ in,
                                                  float4* __restrict__ out)
{
    long long blockBase = (long long)(blockIdx.x) * F4_PER_BLOCK;
    int tid = threadIdx.x;

    float4 v[UNROLL];

    #pragma unroll
    for (int u = 0; u < UNROLL; ++u) {
        long long i = blockBase + u * TPB + tid;
        int c4 = (int)(i & 63);
        int t  = (int)((i >> 18) & 15);

        int dt = (c4 < 16) ? 1 : ((c4 < 32) ? -1 : 0);
        int ts = t + dt;
        bool valid = (unsigned)ts < 16u;

        v[u] = make_float4(0.f, 0.f, 0.f, 0.f);
        if (valid) {
            v[u] = __ldcs(&in[i + (long long)dt * BTSTRIDE]);
        }
    }

    #pragma unroll
    for (int u = 0; u < UNROLL; ++u) {
        long long i = blockBase + u * TPB + tid;
        __stcs(&out[i], v[u]);
    }
}

extern "C" void kernel_launch(void* const* d_in, const int* in_sizes, int n_in,
                              void* d_out, int out_size)
{
    const float4* in = (const float4*)d_in[0];
    float4* out = (float4*)d_out;

    int blocks = (int)(N4 / F4_PER_BLOCK); // 2048
    tsm_kernel<<<blocks, TPB>>>(in, out);
}